// round 14
// baseline (speedup 1.0000x reference)
#include <cuda_runtime.h>
#include <cuda_bf16.h>
#include <math.h>
#include <stdint.h>

#define NN 50000
#define EE 600000
#define DD 128
#define GG 8
#define EPSV 1e-5f

typedef unsigned long long ull;

// ---------------- scratch ----------------
__device__ float g_agg[(size_t)NN * DD];
__device__ float g_f[(size_t)NN * DD];
__device__ int   g_degi[NN];
__device__ int   g_rowptr[NN];
__device__ int   g_pos[NN];
__device__ int   g_srcs[EE];
__device__ int   g_bsum[256];
__device__ float g_sumf[GG * DD];
__device__ float g_sumf2[GG * DD];
__device__ float g_cnt[GG];

__device__ __forceinline__ int wscan_incl(int v, int lane) {
#pragma unroll
    for (int o = 1; o < 32; o <<= 1) {
        int t = __shfl_up_sync(0xffffffff, v, o);
        if (lane >= o) v += t;
    }
    return v;
}

// ---------------- K0: zero ----------------
__global__ void k_zero() {
    int i = blockIdx.x * blockDim.x + threadIdx.x;
    if (i < NN) g_degi[i] = 0;
    if (i < GG * DD) { g_sumf[i] = 0.f; g_sumf2[i] = 0.f; }
    if (i < GG) g_cnt[i] = 0.f;
}

// ---------------- K1: degree histogram ----------------
__global__ void k_hist(const int* __restrict__ ei, int E) {
    int i = blockIdx.x * blockDim.x + threadIdx.x;
    if (i < E) atomicAdd(&g_degi[__ldg(&ei[E + i])], 1);
}

// ---------------- K2a: block-local exclusive scan + graph node counts ----------------
__global__ void k_scan1(const int* __restrict__ batch, int n) {
    __shared__ int wsum[8];
    __shared__ int hist[GG];
    int tid = threadIdx.x, lane = tid & 31, wd = tid >> 5;
    if (tid < GG) hist[tid] = 0;
    __syncthreads();
    int i = blockIdx.x * 256 + tid;
    int v = (i < n) ? g_degi[i] : 0;
    if (i < n) atomicAdd(&hist[__ldg(&batch[i])], 1);
    int inc = wscan_incl(v, lane);
    if (lane == 31) wsum[wd] = inc;
    __syncthreads();
    if (wd == 0) {
        int s = (lane < 8) ? wsum[lane] : 0;
        int si = wscan_incl(s, lane);
        if (lane < 8) wsum[lane] = si - s;
    }
    __syncthreads();
    int excl = inc - v + wsum[wd];
    if (i < n) g_rowptr[i] = excl;
    if (tid == 255) g_bsum[blockIdx.x] = excl + v;
    if (tid < GG && hist[tid] > 0) atomicAdd(&g_cnt[tid], (float)hist[tid]);
}

// ---------------- K2b: scan block sums (deterministic node order) ----------------
__global__ void k_scan2(int nb) {
    __shared__ int wsum[8];
    int tid = threadIdx.x, lane = tid & 31, wd = tid >> 5;
    int v = (tid < nb) ? g_bsum[tid] : 0;
    int inc = wscan_incl(v, lane);
    if (lane == 31) wsum[wd] = inc;
    __syncthreads();
    if (wd == 0) {
        int s = (lane < 8) ? wsum[lane] : 0;
        int si = wscan_incl(s, lane);
        if (lane < 8) wsum[lane] = si - s;
    }
    __syncthreads();
    if (tid < nb) g_bsum[tid] = inc - v + wsum[wd];
}

// ---------------- K2c: add block offsets; init pos = rowptr ----------------
__global__ void k_scan3(int n) {
    int i = blockIdx.x * blockDim.x + threadIdx.x;
    if (i < n) {
        int rp = g_rowptr[i] + g_bsum[i >> 8];
        g_rowptr[i] = rp;
        g_pos[i] = rp;
    }
}

// ---------------- K3: fill CSR source lists (single atomic per edge) ----------------
__global__ void k_fill(const int* __restrict__ ei, int E) {
    int e = blockIdx.x * blockDim.x + threadIdx.x;
    if (e >= E) return;
    int s = __ldg(&ei[e]);
    int d = __ldg(&ei[E + e]);
    g_srcs[atomicAdd(&g_pos[d], 1)] = s;
}

// ---------------- K4: gather-aggregate (1 warp/node) -> mean, unroll 4 ----------------
__global__ void k_gather(const float* __restrict__ x, int n) {
    int gt = blockIdx.x * blockDim.x + threadIdx.x;
    int w = gt >> 5, lane = gt & 31;
    if (w >= n) return;
    int start = g_rowptr[w];
    int deg = g_degi[w];
    float4 acc = make_float4(0.f, 0.f, 0.f, 0.f);
    int j = 0;
    for (; j + 4 <= deg; j += 4) {
        int s0 = __ldg(&g_srcs[start + j]);
        int s1 = __ldg(&g_srcs[start + j + 1]);
        int s2 = __ldg(&g_srcs[start + j + 2]);
        int s3 = __ldg(&g_srcs[start + j + 3]);
        float4 v0 = __ldg(&((const float4*)x)[(size_t)s0 * 32 + lane]);
        float4 v1 = __ldg(&((const float4*)x)[(size_t)s1 * 32 + lane]);
        float4 v2 = __ldg(&((const float4*)x)[(size_t)s2 * 32 + lane]);
        float4 v3 = __ldg(&((const float4*)x)[(size_t)s3 * 32 + lane]);
        acc.x += (v0.x + v1.x) + (v2.x + v3.x);
        acc.y += (v0.y + v1.y) + (v2.y + v3.y);
        acc.z += (v0.z + v1.z) + (v2.z + v3.z);
        acc.w += (v0.w + v1.w) + (v2.w + v3.w);
    }
    for (; j < deg; ++j) {
        int s0 = __ldg(&g_srcs[start + j]);
        float4 v0 = __ldg(&((const float4*)x)[(size_t)s0 * 32 + lane]);
        acc.x += v0.x; acc.y += v0.y; acc.z += v0.z; acc.w += v0.w;
    }
    float iv = 1.0f / fmaxf((float)deg, 1.0f);
    acc.x *= iv; acc.y *= iv; acc.z *= iv; acc.w *= iv;
    ((float4*)g_agg)[(size_t)w * 32 + lane] = acc;
}

// ---------------- K5: mma.sync bf16-split GEMM (128x128, 512 thr — R9 config) ----------------
#define TPITCH 80
#define TSIZE  (128 * TPITCH)

#define LDM4(r, a) \
    asm volatile("ldmatrix.sync.aligned.m8n8.x4.shared.b16 {%0,%1,%2,%3}, [%4];" \
                 : "=r"((r)[0]), "=r"((r)[1]), "=r"((r)[2]), "=r"((r)[3]) : "r"(a))

#define MMA(c, A, b0, b1) \
    asm volatile("mma.sync.aligned.m16n8k16.row.col.f32.bf16.bf16.f32 " \
                 "{%0,%1,%2,%3},{%4,%5,%6,%7},{%8,%9},{%0,%1,%2,%3};" \
                 : "+f"((c)[0]), "+f"((c)[1]), "+f"((c)[2]), "+f"((c)[3]) \
                 : "r"((A)[0]), "r"((A)[1]), "r"((A)[2]), "r"((A)[3]), "r"(b0), "r"(b1))

__device__ __forceinline__ void cvt_store8(char* hi, char* lo, uint32_t off,
                                           float4 u, float4 v) {
    float f[8] = {u.x, u.y, u.z, u.w, v.x, v.y, v.z, v.w};
    uint32_t H[4], L[4];
#pragma unroll
    for (int i = 0; i < 4; ++i) {
        __nv_bfloat16 h0 = __float2bfloat16(f[2 * i]);
        __nv_bfloat16 h1 = __float2bfloat16(f[2 * i + 1]);
        float r0 = f[2 * i] - __bfloat162float(h0);
        float r1 = f[2 * i + 1] - __bfloat162float(h1);
        __nv_bfloat16 l0 = __float2bfloat16(r0);
        __nv_bfloat16 l1 = __float2bfloat16(r1);
        __nv_bfloat162 hh(h0, h1), ll(l0, l1);
        H[i] = *(uint32_t*)&hh;
        L[i] = *(uint32_t*)&ll;
    }
    *(uint4*)(hi + off) = make_uint4(H[0], H[1], H[2], H[3]);
    *(uint4*)(lo + off) = make_uint4(L[0], L[1], L[2], L[3]);
}

__global__ __launch_bounds__(512) void k_mma(
    const float* __restrict__ x, const float* __restrict__ Wl,
    const float* __restrict__ bl, const float* __restrict__ Wr,
    const int* __restrict__ batch, int n)
{
    __shared__ __align__(16) char sm[4 * TSIZE];   // Ahi | Alo | Bhi | Blo = 40KB
    char* sAhi = sm;
    char* sAlo = sm + TSIZE;
    char* sBhi = sm + 2 * TSIZE;
    char* sBlo = sm + 3 * TSIZE;

    const int tid = threadIdx.x;
    const int wid = tid >> 5;
    const int lane = tid & 31;
    const int wm = wid >> 2;
    const int wn = wid & 3;
    const int row0 = blockIdx.x * 128;

    const int srow = tid >> 2;
    const int sgc = tid & 3;
    const uint32_t soff = srow * TPITCH + sgc * 16;

    float acc[2][4][4];
#pragma unroll
    for (int mi = 0; mi < 2; ++mi)
#pragma unroll
        for (int ni = 0; ni < 4; ++ni)
#pragma unroll
            for (int t = 0; t < 4; ++t) acc[mi][ni][t] = 0.f;

    float4 pa[2], pb[2];
    auto load_chunk = [&](int c) {
        const float4* As = (c < 4) ? (const float4*)g_agg : (const float4*)x;
        const float4* Bs = (c < 4) ? (const float4*)Wl : (const float4*)Wr;
        int fq = (c & 3) * 8 + sgc * 2;
        int gr = row0 + srow;
        if (gr < n) {
            pa[0] = __ldg(&As[(size_t)gr * 32 + fq]);
            pa[1] = __ldg(&As[(size_t)gr * 32 + fq + 1]);
        } else {
            pa[0] = make_float4(0.f, 0.f, 0.f, 0.f);
            pa[1] = pa[0];
        }
        pb[0] = __ldg(&Bs[(size_t)srow * 32 + fq]);
        pb[1] = __ldg(&Bs[(size_t)srow * 32 + fq + 1]);
    };

    const uint32_t a_base =
        (uint32_t)((wm * 32 + (lane & 7) + ((lane >> 3) & 1) * 8) * TPITCH
                   + (lane >> 4) * 16);
    const uint32_t b_base =
        (uint32_t)((wn * 32 + (lane & 7) + (lane >> 4) * 8) * TPITCH
                   + ((lane >> 3) & 1) * 16);

    uint32_t smb = (uint32_t)__cvta_generic_to_shared(sm);
    uint32_t aAhi = smb + a_base;
    uint32_t aAlo = smb + TSIZE + a_base;
    uint32_t aBhi = smb + 2 * TSIZE + b_base;
    uint32_t aBlo = smb + 3 * TSIZE + b_base;

    load_chunk(0);

    for (int c = 0; c < 8; ++c) {
        __syncthreads();
        cvt_store8(sAhi, sAlo, soff, pa[0], pa[1]);
        cvt_store8(sBhi, sBlo, soff, pb[0], pb[1]);
        __syncthreads();
        if (c < 7) load_chunk(c + 1);

#pragma unroll
        for (int s = 0; s < 2; ++s) {
            uint32_t Ah[2][4], Al[2][4], Bh[2][4], Bl[2][4];
            LDM4(Ah[0], aAhi + s * 32);
            LDM4(Ah[1], aAhi + 16 * TPITCH + s * 32);
            LDM4(Al[0], aAlo + s * 32);
            LDM4(Al[1], aAlo + 16 * TPITCH + s * 32);
            LDM4(Bh[0], aBhi + s * 32);
            LDM4(Bh[1], aBhi + 16 * TPITCH + s * 32);
            LDM4(Bl[0], aBlo + s * 32);
            LDM4(Bl[1], aBlo + 16 * TPITCH + s * 32);
#pragma unroll
            for (int mi = 0; mi < 2; ++mi)
#pragma unroll
                for (int ni = 0; ni < 4; ++ni) {
                    uint32_t b0h = Bh[ni >> 1][(ni & 1) * 2];
                    uint32_t b1h = Bh[ni >> 1][(ni & 1) * 2 + 1];
                    uint32_t b0l = Bl[ni >> 1][(ni & 1) * 2];
                    uint32_t b1l = Bl[ni >> 1][(ni & 1) * 2 + 1];
                    MMA(acc[mi][ni], Ah[mi], b0h, b1h);
                    MMA(acc[mi][ni], Ah[mi], b0l, b1l);
                    MMA(acc[mi][ni], Al[mi], b0h, b1h);
                }
        }
    }

    // ---- epilogue ----
    const int qr = lane >> 2;
    const int qc = lane & 3;
    const int rl = row0 + wm * 32;

    int g0 = -1;
    if (rl < n) g0 = __ldg(&batch[rl]);
    bool uniform = ((rl + 31) < n) && (__ldg(&batch[rl + 31]) == g0);

    float2 bias[4];
#pragma unroll
    for (int ni = 0; ni < 4; ++ni)
        bias[ni] = *(const float2*)&bl[wn * 32 + ni * 8 + 2 * qc];

    float sf[4][2], sq[4][2];
#pragma unroll
    for (int ni = 0; ni < 4; ++ni) { sf[ni][0] = sf[ni][1] = 0.f; sq[ni][0] = sq[ni][1] = 0.f; }

#pragma unroll
    for (int j = 0; j < 4; ++j) {
        int row = rl + qr + j * 8;
        bool v = row < n;
        int mi = j >> 1, h = j & 1;
        float fv[4][2];
#pragma unroll
        for (int ni = 0; ni < 4; ++ni) {
#pragma unroll
            for (int t = 0; t < 2; ++t) {
                float b = t ? bias[ni].y : bias[ni].x;
                float val = acc[mi][ni][h * 2 + t] + b;
                fv[ni][t] = 0.5f * val * (1.0f + erff(val * 0.70710678118654752f));
            }
        }
        if (v) {
#pragma unroll
            for (int ni = 0; ni < 4; ++ni)
                *(float2*)&g_f[(size_t)row * DD + wn * 32 + ni * 8 + 2 * qc] =
                    make_float2(fv[ni][0], fv[ni][1]);
        }
        if (uniform) {
#pragma unroll
            for (int ni = 0; ni < 4; ++ni)
#pragma unroll
                for (int t = 0; t < 2; ++t) {
                    sf[ni][t] += fv[ni][t];
                    sq[ni][t] += fv[ni][t] * fv[ni][t];
                }
        } else if (v) {
            int g = __ldg(&batch[row]);
#pragma unroll
            for (int ni = 0; ni < 4; ++ni)
#pragma unroll
                for (int t = 0; t < 2; ++t) {
                    atomicAdd(&g_sumf[g * DD + wn * 32 + ni * 8 + 2 * qc + t], fv[ni][t]);
                    atomicAdd(&g_sumf2[g * DD + wn * 32 + ni * 8 + 2 * qc + t],
                              fv[ni][t] * fv[ni][t]);
                }
        }
    }

    if (uniform) {
#pragma unroll
        for (int mask = 4; mask <= 16; mask <<= 1) {
#pragma unroll
            for (int ni = 0; ni < 4; ++ni)
#pragma unroll
                for (int t = 0; t < 2; ++t) {
                    sf[ni][t] += __shfl_xor_sync(0xffffffff, sf[ni][t], mask);
                    sq[ni][t] += __shfl_xor_sync(0xffffffff, sq[ni][t], mask);
                }
        }
        if (qr == 0) {
#pragma unroll
            for (int ni = 0; ni < 4; ++ni)
#pragma unroll
                for (int t = 0; t < 2; ++t) {
                    atomicAdd(&g_sumf[g0 * DD + wn * 32 + ni * 8 + 2 * qc + t], sf[ni][t]);
                    atomicAdd(&g_sumf2[g0 * DD + wn * 32 + ni * 8 + 2 * qc + t], sq[ni][t]);
                }
        }
    }
}

// ---------------- K6: fused norm-fold + out = f*scaleA + shiftB + x ----------------
__global__ void k_out(const float* __restrict__ x, const int* __restrict__ batch,
                      const float* __restrict__ gw, const float* __restrict__ gb,
                      const float* __restrict__ ms,
                      float* __restrict__ out, int n) {
    __shared__ float sS[GG * DD];
    __shared__ float sB[GG * DD];
    int tid = threadIdx.x;
    // fold stats into per-(graph,col) scale/shift (4 per thread @ 256 threads)
#pragma unroll
    for (int k = 0; k < 4; ++k) {
        int i = tid + k * 256;
        int c = i & 127;
        int g = i >> 7;
        float cnt = fmaxf(g_cnt[g], 1.0f);
        float m = g_sumf[i] / cnt;
        float e2 = g_sumf2[i] / cnt;
        float s = __ldg(&ms[c]);
        float var = e2 - (2.0f * s - s * s) * m * m;
        var = fmaxf(var, 0.0f);
        float inv = rsqrtf(var + EPSV);
        float w = __ldg(&gw[c]);
        sS[i] = inv * w;
        sB[i] = __ldg(&gb[c]) - s * m * inv * w;
    }
    __syncthreads();

    int i = blockIdx.x * blockDim.x + tid;
    if (i >= n * 32) return;
    int row = i >> 5;
    int c4 = i & 31;
    int g = batch[row];
    float4 f = ((const float4*)g_f)[i];
    float4 s = *(const float4*)&sS[g * DD + c4 * 4];
    float4 b = *(const float4*)&sB[g * DD + c4 * 4];
    float4 xv = ((const float4*)x)[i];
    float4 o;
    o.x = fmaf(f.x, s.x, b.x) + xv.x;
    o.y = fmaf(f.y, s.y, b.y) + xv.y;
    o.z = fmaf(f.z, s.z, b.z) + xv.z;
    o.w = fmaf(f.w, s.w, b.w) + xv.w;
    ((float4*)out)[i] = o;
}

// ---------------- host launcher ----------------
extern "C" void kernel_launch(void* const* d_in, const int* in_sizes, int n_in,
                              void* d_out, int out_size) {
    const float* x     = (const float*)d_in[0];
    const int*   ei    = (const int*)d_in[1];
    const int*   batch = (const int*)d_in[2];
    const float* Wl = (const float*)d_in[4];
    const float* bl = (const float*)d_in[5];
    const float* Wr = (const float*)d_in[6];
    const float* gw = (const float*)d_in[7];
    const float* gb = (const float*)d_in[8];
    const float* ms = (const float*)d_in[9];

    int n = in_sizes[0] / DD;
    int E = in_sizes[1] / 2;
    int nb = (n + 255) / 256;

    k_zero<<<(NN + 255) / 256, 256>>>();
    k_hist<<<(E + 255) / 256, 256>>>(ei, E);
    k_scan1<<<nb, 256>>>(batch, n);
    k_scan2<<<1, 256>>>(nb);
    k_scan3<<<nb, 256>>>(n);
    k_fill<<<(E + 255) / 256, 256>>>(ei, E);
    k_gather<<<((size_t)n * 32 + 255) / 256, 256>>>(x, n);
    k_mma<<<(n + 127) / 128, 512>>>(x, Wl, bl, Wr, batch, n);
    k_out<<<(n * 32 + 255) / 256, 256>>>(x, batch, gw, gb, ms, (float*)d_out, n);
}

// round 16
// speedup vs baseline: 1.0674x; 1.0674x over previous
#include <cuda_runtime.h>
#include <cuda_bf16.h>
#include <math.h>
#include <stdint.h>

#define NN 50000
#define EE 600000
#define DD 128
#define GG 8
#define EPSV 1e-5f

typedef unsigned long long ull;

// ---------------- scratch ----------------
__device__ float g_agg[(size_t)NN * DD];
__device__ float g_f[(size_t)NN * DD];
__device__ int   g_degi[NN];
__device__ int   g_rowptr[NN];
__device__ int   g_pos[NN];
__device__ int   g_srcs[EE];
__device__ int   g_bsum[256];
__device__ float g_sumf[GG * DD];
__device__ float g_sumf2[GG * DD];
__device__ float g_cnt[GG];
__device__ float g_scaleA[GG * DD];
__device__ float g_shiftB[GG * DD];

__device__ __forceinline__ int wscan_incl(int v, int lane) {
#pragma unroll
    for (int o = 1; o < 32; o <<= 1) {
        int t = __shfl_up_sync(0xffffffff, v, o);
        if (lane >= o) v += t;
    }
    return v;
}

// ---------------- K0: zero ----------------
__global__ void k_zero() {
    int i = blockIdx.x * blockDim.x + threadIdx.x;
    if (i < NN) g_degi[i] = 0;
    if (i < GG * DD) { g_sumf[i] = 0.f; g_sumf2[i] = 0.f; }
    if (i < GG) g_cnt[i] = 0.f;
}

// ---------------- K1: degree histogram ----------------
__global__ void k_hist(const int* __restrict__ ei, int E) {
    int i = blockIdx.x * blockDim.x + threadIdx.x;
    if (i < E) atomicAdd(&g_degi[__ldg(&ei[E + i])], 1);
}

// ---------------- K2a: block-local exclusive scan + graph node counts ----------------
__global__ void k_scan1(const int* __restrict__ batch, int n) {
    __shared__ int wsum[8];
    __shared__ int hist[GG];
    int tid = threadIdx.x, lane = tid & 31, wd = tid >> 5;
    if (tid < GG) hist[tid] = 0;
    __syncthreads();
    int i = blockIdx.x * 256 + tid;
    int v = (i < n) ? g_degi[i] : 0;
    if (i < n) atomicAdd(&hist[__ldg(&batch[i])], 1);
    int inc = wscan_incl(v, lane);
    if (lane == 31) wsum[wd] = inc;
    __syncthreads();
    if (wd == 0) {
        int s = (lane < 8) ? wsum[lane] : 0;
        int si = wscan_incl(s, lane);
        if (lane < 8) wsum[lane] = si - s;
    }
    __syncthreads();
    int excl = inc - v + wsum[wd];
    if (i < n) g_rowptr[i] = excl;
    if (tid == 255) g_bsum[blockIdx.x] = excl + v;
    if (tid < GG && hist[tid] > 0) atomicAdd(&g_cnt[tid], (float)hist[tid]);
}

// ---------------- K2b: scan block sums (deterministic node order) ----------------
__global__ void k_scan2(int nb) {
    __shared__ int wsum[8];
    int tid = threadIdx.x, lane = tid & 31, wd = tid >> 5;
    int v = (tid < nb) ? g_bsum[tid] : 0;
    int inc = wscan_incl(v, lane);
    if (lane == 31) wsum[wd] = inc;
    __syncthreads();
    if (wd == 0) {
        int s = (lane < 8) ? wsum[lane] : 0;
        int si = wscan_incl(s, lane);
        if (lane < 8) wsum[lane] = si - s;
    }
    __syncthreads();
    if (tid < nb) g_bsum[tid] = inc - v + wsum[wd];
}

// ---------------- K2c: add block offsets; init pos = rowptr ----------------
__global__ void k_scan3(int n) {
    int i = blockIdx.x * blockDim.x + threadIdx.x;
    if (i < n) {
        int rp = g_rowptr[i] + g_bsum[i >> 8];
        g_rowptr[i] = rp;
        g_pos[i] = rp;
    }
}

// ---------------- K3: fill CSR source lists (single atomic per edge) ----------------
__global__ void k_fill(const int* __restrict__ ei, int E) {
    int e = blockIdx.x * blockDim.x + threadIdx.x;
    if (e >= E) return;
    int s = __ldg(&ei[e]);
    int d = __ldg(&ei[E + e]);
    g_srcs[atomicAdd(&g_pos[d], 1)] = s;
}

// ---------------- K4: gather-aggregate (1 warp/node) -> mean, unroll 4 ----------------
__global__ void k_gather(const float* __restrict__ x, int n) {
    int gt = blockIdx.x * blockDim.x + threadIdx.x;
    int w = gt >> 5, lane = gt & 31;
    if (w >= n) return;
    int start = g_rowptr[w];
    int deg = g_degi[w];
    float4 acc = make_float4(0.f, 0.f, 0.f, 0.f);
    int j = 0;
    for (; j + 4 <= deg; j += 4) {
        int s0 = __ldg(&g_srcs[start + j]);
        int s1 = __ldg(&g_srcs[start + j + 1]);
        int s2 = __ldg(&g_srcs[start + j + 2]);
        int s3 = __ldg(&g_srcs[start + j + 3]);
        float4 v0 = __ldg(&((const float4*)x)[(size_t)s0 * 32 + lane]);
        float4 v1 = __ldg(&((const float4*)x)[(size_t)s1 * 32 + lane]);
        float4 v2 = __ldg(&((const float4*)x)[(size_t)s2 * 32 + lane]);
        float4 v3 = __ldg(&((const float4*)x)[(size_t)s3 * 32 + lane]);
        acc.x += (v0.x + v1.x) + (v2.x + v3.x);
        acc.y += (v0.y + v1.y) + (v2.y + v3.y);
        acc.z += (v0.z + v1.z) + (v2.z + v3.z);
        acc.w += (v0.w + v1.w) + (v2.w + v3.w);
    }
    for (; j < deg; ++j) {
        int s0 = __ldg(&g_srcs[start + j]);
        float4 v0 = __ldg(&((const float4*)x)[(size_t)s0 * 32 + lane]);
        acc.x += v0.x; acc.y += v0.y; acc.z += v0.z; acc.w += v0.w;
    }
    float iv = 1.0f / fmaxf((float)deg, 1.0f);
    acc.x *= iv; acc.y *= iv; acc.z *= iv; acc.w *= iv;
    ((float4*)g_agg)[(size_t)w * 32 + lane] = acc;
}

// ---------------- K5: mma.sync bf16-split GEMM (128x128, 512 thr — R9 config) ----------------
#define TPITCH 80
#define TSIZE  (128 * TPITCH)

#define LDM4(r, a) \
    asm volatile("ldmatrix.sync.aligned.m8n8.x4.shared.b16 {%0,%1,%2,%3}, [%4];" \
                 : "=r"((r)[0]), "=r"((r)[1]), "=r"((r)[2]), "=r"((r)[3]) : "r"(a))

#define MMA(c, A, b0, b1) \
    asm volatile("mma.sync.aligned.m16n8k16.row.col.f32.bf16.bf16.f32 " \
                 "{%0,%1,%2,%3},{%4,%5,%6,%7},{%8,%9},{%0,%1,%2,%3};" \
                 : "+f"((c)[0]), "+f"((c)[1]), "+f"((c)[2]), "+f"((c)[3]) \
                 : "r"((A)[0]), "r"((A)[1]), "r"((A)[2]), "r"((A)[3]), "r"(b0), "r"(b1))

__device__ __forceinline__ void cvt_store8(char* hi, char* lo, uint32_t off,
                                           float4 u, float4 v) {
    float f[8] = {u.x, u.y, u.z, u.w, v.x, v.y, v.z, v.w};
    uint32_t H[4], L[4];
#pragma unroll
    for (int i = 0; i < 4; ++i) {
        __nv_bfloat16 h0 = __float2bfloat16(f[2 * i]);
        __nv_bfloat16 h1 = __float2bfloat16(f[2 * i + 1]);
        float r0 = f[2 * i] - __bfloat162float(h0);
        float r1 = f[2 * i + 1] - __bfloat162float(h1);
        __nv_bfloat16 l0 = __float2bfloat16(r0);
        __nv_bfloat16 l1 = __float2bfloat16(r1);
        __nv_bfloat162 hh(h0, h1), ll(l0, l1);
        H[i] = *(uint32_t*)&hh;
        L[i] = *(uint32_t*)&ll;
    }
    *(uint4*)(hi + off) = make_uint4(H[0], H[1], H[2], H[3]);
    *(uint4*)(lo + off) = make_uint4(L[0], L[1], L[2], L[3]);
}

__global__ __launch_bounds__(512) void k_mma(
    const float* __restrict__ x, const float* __restrict__ Wl,
    const float* __restrict__ bl, const float* __restrict__ Wr,
    const int* __restrict__ batch, int n)
{
    __shared__ __align__(16) char sm[4 * TSIZE];   // Ahi | Alo | Bhi | Blo = 40KB
    char* sAhi = sm;
    char* sAlo = sm + TSIZE;
    char* sBhi = sm + 2 * TSIZE;
    char* sBlo = sm + 3 * TSIZE;

    const int tid = threadIdx.x;
    const int wid = tid >> 5;
    const int lane = tid & 31;
    const int wm = wid >> 2;
    const int wn = wid & 3;
    const int row0 = blockIdx.x * 128;

    const int srow = tid >> 2;
    const int sgc = tid & 3;
    const uint32_t soff = srow * TPITCH + sgc * 16;

    float acc[2][4][4];
#pragma unroll
    for (int mi = 0; mi < 2; ++mi)
#pragma unroll
        for (int ni = 0; ni < 4; ++ni)
#pragma unroll
            for (int t = 0; t < 4; ++t) acc[mi][ni][t] = 0.f;

    float4 pa[2], pb[2];
    auto load_chunk = [&](int c) {
        const float4* As = (c < 4) ? (const float4*)g_agg : (const float4*)x;
        const float4* Bs = (c < 4) ? (const float4*)Wl : (const float4*)Wr;
        int fq = (c & 3) * 8 + sgc * 2;
        int gr = row0 + srow;
        if (gr < n) {
            pa[0] = __ldg(&As[(size_t)gr * 32 + fq]);
            pa[1] = __ldg(&As[(size_t)gr * 32 + fq + 1]);
        } else {
            pa[0] = make_float4(0.f, 0.f, 0.f, 0.f);
            pa[1] = pa[0];
        }
        pb[0] = __ldg(&Bs[(size_t)srow * 32 + fq]);
        pb[1] = __ldg(&Bs[(size_t)srow * 32 + fq + 1]);
    };

    const uint32_t a_base =
        (uint32_t)((wm * 32 + (lane & 7) + ((lane >> 3) & 1) * 8) * TPITCH
                   + (lane >> 4) * 16);
    const uint32_t b_base =
        (uint32_t)((wn * 32 + (lane & 7) + (lane >> 4) * 8) * TPITCH
                   + ((lane >> 3) & 1) * 16);

    uint32_t smb = (uint32_t)__cvta_generic_to_shared(sm);
    uint32_t aAhi = smb + a_base;
    uint32_t aAlo = smb + TSIZE + a_base;
    uint32_t aBhi = smb + 2 * TSIZE + b_base;
    uint32_t aBlo = smb + 3 * TSIZE + b_base;

    load_chunk(0);

    for (int c = 0; c < 8; ++c) {
        __syncthreads();
        cvt_store8(sAhi, sAlo, soff, pa[0], pa[1]);
        cvt_store8(sBhi, sBlo, soff, pb[0], pb[1]);
        __syncthreads();
        if (c < 7) load_chunk(c + 1);

#pragma unroll
        for (int s = 0; s < 2; ++s) {
            uint32_t Ah[2][4], Al[2][4], Bh[2][4], Bl[2][4];
            LDM4(Ah[0], aAhi + s * 32);
            LDM4(Ah[1], aAhi + 16 * TPITCH + s * 32);
            LDM4(Al[0], aAlo + s * 32);
            LDM4(Al[1], aAlo + 16 * TPITCH + s * 32);
            LDM4(Bh[0], aBhi + s * 32);
            LDM4(Bh[1], aBhi + 16 * TPITCH + s * 32);
            LDM4(Bl[0], aBlo + s * 32);
            LDM4(Bl[1], aBlo + 16 * TPITCH + s * 32);
#pragma unroll
            for (int mi = 0; mi < 2; ++mi)
#pragma unroll
                for (int ni = 0; ni < 4; ++ni) {
                    uint32_t b0h = Bh[ni >> 1][(ni & 1) * 2];
                    uint32_t b1h = Bh[ni >> 1][(ni & 1) * 2 + 1];
                    uint32_t b0l = Bl[ni >> 1][(ni & 1) * 2];
                    uint32_t b1l = Bl[ni >> 1][(ni & 1) * 2 + 1];
                    MMA(acc[mi][ni], Ah[mi], b0h, b1h);
                    MMA(acc[mi][ni], Ah[mi], b0l, b1l);
                    MMA(acc[mi][ni], Al[mi], b0h, b1h);
                }
        }
    }

    // ---- epilogue ----
    const int qr = lane >> 2;
    const int qc = lane & 3;
    const int rl = row0 + wm * 32;

    int g0 = -1;
    if (rl < n) g0 = __ldg(&batch[rl]);
    bool uniform = ((rl + 31) < n) && (__ldg(&batch[rl + 31]) == g0);

    float2 bias[4];
#pragma unroll
    for (int ni = 0; ni < 4; ++ni)
        bias[ni] = *(const float2*)&bl[wn * 32 + ni * 8 + 2 * qc];

    float sf[4][2], sq[4][2];
#pragma unroll
    for (int ni = 0; ni < 4; ++ni) { sf[ni][0] = sf[ni][1] = 0.f; sq[ni][0] = sq[ni][1] = 0.f; }

#pragma unroll
    for (int j = 0; j < 4; ++j) {
        int row = rl + qr + j * 8;
        bool v = row < n;
        int mi = j >> 1, h = j & 1;
        float fv[4][2];
#pragma unroll
        for (int ni = 0; ni < 4; ++ni) {
#pragma unroll
            for (int t = 0; t < 2; ++t) {
                float b = t ? bias[ni].y : bias[ni].x;
                float val = acc[mi][ni][h * 2 + t] + b;
                fv[ni][t] = 0.5f * val * (1.0f + erff(val * 0.70710678118654752f));
            }
        }
        if (v) {
#pragma unroll
            for (int ni = 0; ni < 4; ++ni)
                *(float2*)&g_f[(size_t)row * DD + wn * 32 + ni * 8 + 2 * qc] =
                    make_float2(fv[ni][0], fv[ni][1]);
        }
        if (uniform) {
#pragma unroll
            for (int ni = 0; ni < 4; ++ni)
#pragma unroll
                for (int t = 0; t < 2; ++t) {
                    sf[ni][t] += fv[ni][t];
                    sq[ni][t] += fv[ni][t] * fv[ni][t];
                }
        } else if (v) {
            int g = __ldg(&batch[row]);
#pragma unroll
            for (int ni = 0; ni < 4; ++ni)
#pragma unroll
                for (int t = 0; t < 2; ++t) {
                    atomicAdd(&g_sumf[g * DD + wn * 32 + ni * 8 + 2 * qc + t], fv[ni][t]);
                    atomicAdd(&g_sumf2[g * DD + wn * 32 + ni * 8 + 2 * qc + t],
                              fv[ni][t] * fv[ni][t]);
                }
        }
    }

    if (uniform) {
#pragma unroll
        for (int mask = 4; mask <= 16; mask <<= 1) {
#pragma unroll
            for (int ni = 0; ni < 4; ++ni)
#pragma unroll
                for (int t = 0; t < 2; ++t) {
                    sf[ni][t] += __shfl_xor_sync(0xffffffff, sf[ni][t], mask);
                    sq[ni][t] += __shfl_xor_sync(0xffffffff, sq[ni][t], mask);
                }
        }
        if (qr == 0) {
#pragma unroll
            for (int ni = 0; ni < 4; ++ni)
#pragma unroll
                for (int t = 0; t < 2; ++t) {
                    atomicAdd(&g_sumf[g0 * DD + wn * 32 + ni * 8 + 2 * qc + t], sf[ni][t]);
                    atomicAdd(&g_sumf2[g0 * DD + wn * 32 + ni * 8 + 2 * qc + t], sq[ni][t]);
                }
        }
    }
}

// ---------------- K6: fold stats (separate grid-1 launch — measured best) ----------------
__global__ void k_norm(const float* __restrict__ gw, const float* __restrict__ gb,
                       const float* __restrict__ ms) {
    int i = threadIdx.x;
    int c = i & 127;
    int g = i >> 7;
    float cnt = fmaxf(g_cnt[g], 1.0f);
    float m = g_sumf[i] / cnt;
    float e2 = g_sumf2[i] / cnt;
    float s = ms[c];
    float var = e2 - (2.0f * s - s * s) * m * m;
    var = fmaxf(var, 0.0f);
    float inv = rsqrtf(var + EPSV);
    float w = gw[c];
    g_scaleA[i] = inv * w;
    g_shiftB[i] = gb[c] - s * m * inv * w;
}

// ---------------- K7: out = f*scaleA + shiftB + x ----------------
__global__ void k_out(const float* __restrict__ x, const int* __restrict__ batch,
                      float* __restrict__ out, int n) {
    int i = blockIdx.x * blockDim.x + threadIdx.x;
    if (i >= n * 32) return;
    int row = i >> 5;
    int c4 = i & 31;
    int g = batch[row];
    float4 f = ((const float4*)g_f)[i];
    float4 s = __ldg(&((const float4*)g_scaleA)[g * 32 + c4]);
    float4 b = __ldg(&((const float4*)g_shiftB)[g * 32 + c4]);
    float4 xv = ((const float4*)x)[i];
    float4 o;
    o.x = fmaf(f.x, s.x, b.x) + xv.x;
    o.y = fmaf(f.y, s.y, b.y) + xv.y;
    o.z = fmaf(f.z, s.z, b.z) + xv.z;
    o.w = fmaf(f.w, s.w, b.w) + xv.w;
    ((float4*)out)[i] = o;
}

// ---------------- host launcher ----------------
extern "C" void kernel_launch(void* const* d_in, const int* in_sizes, int n_in,
                              void* d_out, int out_size) {
    const float* x     = (const float*)d_in[0];
    const int*   ei    = (const int*)d_in[1];
    const int*   batch = (const int*)d_in[2];
    const float* Wl = (const float*)d_in[4];
    const float* bl = (const float*)d_in[5];
    const float* Wr = (const float*)d_in[6];
    const float* gw = (const float*)d_in[7];
    const float* gb = (const float*)d_in[8];
    const float* ms = (const float*)d_in[9];

    int n = in_sizes[0] / DD;
    int E = in_sizes[1] / 2;
    int nb = (n + 255) / 256;

    k_zero<<<(NN + 255) / 256, 256>>>();
    k_hist<<<(E + 255) / 256, 256>>>(ei, E);
    k_scan1<<<nb, 256>>>(batch, n);
    k_scan2<<<1, 256>>>(nb);
    k_scan3<<<nb, 256>>>(n);
    k_fill<<<(E + 255) / 256, 256>>>(ei, E);
    k_gather<<<((size_t)n * 32 + 255) / 256, 256>>>(x, n);
    k_mma<<<(n + 127) / 128, 512>>>(x, Wl, bl, Wr, batch, n);
    k_norm<<<1, 1024>>>(gw, gb, ms);
    k_out<<<(n * 32 + 255) / 256, 256>>>(x, batch, (float*)d_out, n);
}